// round 15
// baseline (speedup 1.0000x reference)
#include <cuda_runtime.h>
#include <math.h>

// Problem constants
#define BB   4
#define SS   2048
#define DIM  1024
#define NH   16
#define HD   64
#define MROWS (BB * SS)   // 8192

// Scratch for projected q/k/v and attention context ([B,S,DIM] layout each).
__device__ float g_q[MROWS * DIM];
__device__ float g_k[MROWS * DIM];
__device__ float g_v[MROWS * DIM];
__device__ float g_ctx[MROWS * DIM];

// ---------------------------------------------------------------------------
// GEMM: C[M,1024] = A[M,1024] @ W[1024,1024] + bias[1024]   (all row-major)
// 128x128 block tile, BK=8, 256 threads, 8x8 micro-tile per thread.
// ---------------------------------------------------------------------------
__global__ __launch_bounds__(256)
void gemm_bias_kernel(const float* __restrict__ A,
                      const float* __restrict__ W,
                      const float* __restrict__ bias,
                      float* __restrict__ C) {
    const int N = DIM, K = DIM;
    __shared__ float As[8][128];   // transposed A tile: As[k][row]
    __shared__ float Bs[8][128];   // Bs[k][col]

    const int tid = threadIdx.x;
    const int rm = blockIdx.y * 128;
    const int cn = blockIdx.x * 128;
    const int ty = tid >> 4;        // 0..15
    const int tx = tid & 15;        // 0..15

    const int a_row = tid >> 1;           // 0..127
    const int a_col = (tid & 1) << 2;     // 0 or 4
    const int b_row = tid >> 5;           // 0..7
    const int b_col = (tid & 31) << 2;    // 0..124

    const float* Ap = A + (size_t)(rm + a_row) * K + a_col;
    const float* Wp = W + (size_t)b_row * N + cn + b_col;

    float acc[8][8];
#pragma unroll
    for (int i = 0; i < 8; i++)
#pragma unroll
        for (int j = 0; j < 8; j++) acc[i][j] = 0.f;

    for (int k0 = 0; k0 < K; k0 += 8) {
        float4 av = *(const float4*)(Ap + k0);
        float4 bv = *(const float4*)(Wp + (size_t)k0 * N);
        As[a_col + 0][a_row] = av.x;
        As[a_col + 1][a_row] = av.y;
        As[a_col + 2][a_row] = av.z;
        As[a_col + 3][a_row] = av.w;
        *(float4*)&Bs[b_row][b_col] = bv;
        __syncthreads();

#pragma unroll
        for (int k = 0; k < 8; k++) {
            float4 a0 = *(const float4*)&As[k][ty * 4];
            float4 a1 = *(const float4*)&As[k][ty * 4 + 64];
            float4 b0 = *(const float4*)&Bs[k][tx * 4];
            float4 b1 = *(const float4*)&Bs[k][tx * 4 + 64];
            float ar[8] = {a0.x, a0.y, a0.z, a0.w, a1.x, a1.y, a1.z, a1.w};
            float br[8] = {b0.x, b0.y, b0.z, b0.w, b1.x, b1.y, b1.z, b1.w};
#pragma unroll
            for (int i = 0; i < 8; i++)
#pragma unroll
                for (int j = 0; j < 8; j++)
                    acc[i][j] += ar[i] * br[j];
        }
        __syncthreads();
    }

    // epilogue: add bias, vectorized stores
    float4 bb0 = *(const float4*)(bias + cn + tx * 4);
    float4 bb1 = *(const float4*)(bias + cn + 64 + tx * 4);
#pragma unroll
    for (int ih = 0; ih < 2; ih++) {
#pragma unroll
        for (int ii = 0; ii < 4; ii++) {
            const int i = ih * 4 + ii;
            const int row = rm + ih * 64 + ty * 4 + ii;
            float4 o0, o1;
            o0.x = acc[i][0] + bb0.x;
            o0.y = acc[i][1] + bb0.y;
            o0.z = acc[i][2] + bb0.z;
            o0.w = acc[i][3] + bb0.w;
            o1.x = acc[i][4] + bb1.x;
            o1.y = acc[i][5] + bb1.y;
            o1.z = acc[i][6] + bb1.z;
            o1.w = acc[i][7] + bb1.w;
            *(float4*)(C + (size_t)row * N + cn + tx * 4)      = o0;
            *(float4*)(C + (size_t)row * N + cn + 64 + tx * 4) = o1;
        }
    }
}

// ---------------------------------------------------------------------------
// Flash attention, fp32, D=64, 64-query block per CTA, 64-key tiles.
// Grid: (S/64, H, B) = (32, 16, 4). 256 threads.
// Dynamic SMEM layout (floats):
//   qs  [64][64]      (q * 1/sqrt(64))
//   kts [64][65]      k transposed: kts[d][c]  (pad 65 vs transpose conflicts)
//   vs  [64][64]      v: vs[c][d]              (float4 reads)
//   ss  [64][65]      scores / probabilities
//   maskv[64]         mask * -1e9 for this key tile
// ---------------------------------------------------------------------------
#define ATTN_SMEM_FLOATS (64*64 + 64*65 + 64*64 + 64*65 + 64)
#define ATTN_SMEM_BYTES  (ATTN_SMEM_FLOATS * 4)

__global__ __launch_bounds__(256)
void flash_attn_kernel(const float* __restrict__ maskg,
                       const float* __restrict__ qg_,
                       const float* __restrict__ kg_,
                       const float* __restrict__ vg_,
                       float* __restrict__ ctxg) {
    extern __shared__ float sm[];
    float* qs    = sm;                    // 4096
    float* kts   = qs + 64 * 64;          // 4160
    float* vs    = kts + 64 * 65;         // 4096
    float* ss    = vs + 64 * 64;          // 4160
    float* maskv = ss + 64 * 65;          // 64

    const int tid = threadIdx.x;
    const int qt = blockIdx.x, h = blockIdx.y, b = blockIdx.z;
    const int q0 = qt * 64;
    const int ty = tid >> 4, tx = tid & 15;   // S-compute mapping (4x4 tile)
    const int r_ = tid >> 2, q4 = tid & 3;    // softmax / o-update mapping

    // load q tile, pre-scaled by 1/sqrt(64)
    const float* qg = qg_ + ((size_t)(b * SS + q0)) * DIM + h * HD;
#pragma unroll
    for (int u = 0; u < 4; u++) {
        int idx = tid + u * 256;       // 0..1023
        int r   = idx >> 4;
        int d4  = (idx & 15) << 2;
        float4 v4 = *(const float4*)(qg + (size_t)r * DIM + d4);
        float4 w;
        w.x = v4.x * 0.125f; w.y = v4.y * 0.125f;
        w.z = v4.z * 0.125f; w.w = v4.w * 0.125f;
        *(float4*)&qs[r * 64 + d4] = w;
    }

    float m = -1e30f, l = 0.f;
    float o[16];
#pragma unroll
    for (int j = 0; j < 16; j++) o[j] = 0.f;

    for (int kt = 0; kt < 32; kt++) {
        __syncthreads();   // prior iteration fully consumed kts/vs/ss

        const float* kg = kg_ + ((size_t)(b * SS + kt * 64)) * DIM + h * HD;
        const float* vg = vg_ + ((size_t)(b * SS + kt * 64)) * DIM + h * HD;
#pragma unroll
        for (int u = 0; u < 4; u++) {
            int idx = tid + u * 256;
            int c   = idx >> 4;
            int d4  = (idx & 15) << 2;
            float4 kv = *(const float4*)(kg + (size_t)c * DIM + d4);
            kts[(d4 + 0) * 65 + c] = kv.x;
            kts[(d4 + 1) * 65 + c] = kv.y;
            kts[(d4 + 2) * 65 + c] = kv.z;
            kts[(d4 + 3) * 65 + c] = kv.w;
            float4 vv = *(const float4*)(vg + (size_t)c * DIM + d4);
            *(float4*)&vs[c * 64 + d4] = vv;
        }
        if (tid < 64)
            maskv[tid] = maskg[(size_t)b * SS + kt * 64 + tid] * -1e9f;
        __syncthreads();

        // S = q @ k^T  (each thread: 4x4 tile)
        float sacc[4][4];
#pragma unroll
        for (int i = 0; i < 4; i++)
#pragma unroll
            for (int j = 0; j < 4; j++) sacc[i][j] = 0.f;

#pragma unroll 8
        for (int d = 0; d < 64; d++) {
            float a0 = qs[(ty * 4 + 0) * 64 + d];
            float a1 = qs[(ty * 4 + 1) * 64 + d];
            float a2 = qs[(ty * 4 + 2) * 64 + d];
            float a3 = qs[(ty * 4 + 3) * 64 + d];
            float b0 = kts[d * 65 + tx * 4 + 0];
            float b1 = kts[d * 65 + tx * 4 + 1];
            float b2 = kts[d * 65 + tx * 4 + 2];
            float b3 = kts[d * 65 + tx * 4 + 3];
            sacc[0][0] += a0 * b0; sacc[0][1] += a0 * b1; sacc[0][2] += a0 * b2; sacc[0][3] += a0 * b3;
            sacc[1][0] += a1 * b0; sacc[1][1] += a1 * b1; sacc[1][2] += a1 * b2; sacc[1][3] += a1 * b3;
            sacc[2][0] += a2 * b0; sacc[2][1] += a2 * b1; sacc[2][2] += a2 * b2; sacc[2][3] += a2 * b3;
            sacc[3][0] += a3 * b0; sacc[3][1] += a3 * b1; sacc[3][2] += a3 * b2; sacc[3][3] += a3 * b3;
        }
#pragma unroll
        for (int i = 0; i < 4; i++)
#pragma unroll
            for (int j = 0; j < 4; j++)
                ss[(ty * 4 + i) * 65 + tx * 4 + j] = sacc[i][j] + maskv[tx * 4 + j];
        __syncthreads();

        // online softmax: row r_ handled by its 4 consecutive lanes
        float lmax = -1e30f;
#pragma unroll
        for (int jj = 0; jj < 16; jj++)
            lmax = fmaxf(lmax, ss[r_ * 65 + q4 * 16 + jj]);
        lmax = fmaxf(lmax, __shfl_xor_sync(0xffffffffu, lmax, 1));
        lmax = fmaxf(lmax, __shfl_xor_sync(0xffffffffu, lmax, 2));
        float mnew = fmaxf(m, lmax);

        float lsum = 0.f;
#pragma unroll
        for (int jj = 0; jj < 16; jj++) {
            float p = __expf(ss[r_ * 65 + q4 * 16 + jj] - mnew);
            ss[r_ * 65 + q4 * 16 + jj] = p;
            lsum += p;
        }
        lsum += __shfl_xor_sync(0xffffffffu, lsum, 1);
        lsum += __shfl_xor_sync(0xffffffffu, lsum, 2);

        float alpha = __expf(m - mnew);
        l = l * alpha + lsum;
        m = mnew;
#pragma unroll
        for (int j = 0; j < 16; j++) o[j] *= alpha;

        __syncwarp();   // quad-mates' probability writes visible

        // o += P @ V  (thread owns row r_, dim slice q4*16..+15)
#pragma unroll 4
        for (int c = 0; c < 64; c++) {
            float p = ss[r_ * 65 + c];
            const float* vrow = &vs[c * 64 + q4 * 16];
            float4 v0 = *(const float4*)(vrow + 0);
            float4 v1 = *(const float4*)(vrow + 4);
            float4 v2 = *(const float4*)(vrow + 8);
            float4 v3 = *(const float4*)(vrow + 12);
            o[0]  += p * v0.x; o[1]  += p * v0.y; o[2]  += p * v0.z; o[3]  += p * v0.w;
            o[4]  += p * v1.x; o[5]  += p * v1.y; o[6]  += p * v1.z; o[7]  += p * v1.w;
            o[8]  += p * v2.x; o[9]  += p * v2.y; o[10] += p * v2.z; o[11] += p * v2.w;
            o[12] += p * v3.x; o[13] += p * v3.y; o[14] += p * v3.z; o[15] += p * v3.w;
        }
    }

    // epilogue: normalize and write back in [B,S,DIM] layout (heads re-merged)
    float inv = 1.f / l;
    float* og = ctxg + ((size_t)(b * SS + q0 + r_)) * DIM + h * HD + q4 * 16;
#pragma unroll
    for (int j4 = 0; j4 < 4; j4++) {
        float4 w;
        w.x = o[j4 * 4 + 0] * inv;
        w.y = o[j4 * 4 + 1] * inv;
        w.z = o[j4 * 4 + 2] * inv;
        w.w = o[j4 * 4 + 3] * inv;
        *(float4*)(og + j4 * 4) = w;
    }
}

// ---------------------------------------------------------------------------
extern "C" void kernel_launch(void* const* d_in, const int* in_sizes, int n_in,
                              void* d_out, int out_size) {
    const float* Q    = (const float*)d_in[0];
    const float* K    = (const float*)d_in[1];
    const float* V    = (const float*)d_in[2];
    const float* mask = (const float*)d_in[3];
    const float* Wq   = (const float*)d_in[4];
    const float* bq   = (const float*)d_in[5];
    const float* Wk   = (const float*)d_in[6];
    const float* bk   = (const float*)d_in[7];
    const float* Wv   = (const float*)d_in[8];
    const float* bv   = (const float*)d_in[9];
    const float* Wo   = (const float*)d_in[10];
    const float* bo   = (const float*)d_in[11];
    float* out = (float*)d_out;

    float *gq, *gk, *gv, *gctx;
    cudaGetSymbolAddress((void**)&gq,   g_q);
    cudaGetSymbolAddress((void**)&gk,   g_k);
    cudaGetSymbolAddress((void**)&gv,   g_v);
    cudaGetSymbolAddress((void**)&gctx, g_ctx);

    cudaFuncSetAttribute(flash_attn_kernel,
                         cudaFuncAttributeMaxDynamicSharedMemorySize,
                         ATTN_SMEM_BYTES);

    dim3 gemm_grid(DIM / 128, MROWS / 128);   // (8, 64)

    gemm_bias_kernel<<<gemm_grid, 256>>>(Q, Wq, bq, gq);
    gemm_bias_kernel<<<gemm_grid, 256>>>(K, Wk, bk, gk);
    gemm_bias_kernel<<<gemm_grid, 256>>>(V, Wv, bv, gv);

    flash_attn_kernel<<<dim3(SS / 64, NH, BB), 256, ATTN_SMEM_BYTES>>>(
        mask, gq, gk, gv, gctx);

    gemm_bias_kernel<<<gemm_grid, 256>>>(gctx, Wo, bo, out);
}

// round 16
// speedup vs baseline: 1.0729x; 1.0729x over previous
#include <cuda_runtime.h>
#include <math.h>

// Problem constants
#define BB   4
#define SS   2048
#define DIM  1024
#define NH   16
#define HD   64
#define MROWS (BB * SS)   // 8192

// Scratch for projected q/k/v and attention context ([B,S,DIM] layout each).
__device__ float g_q[MROWS * DIM];
__device__ float g_k[MROWS * DIM];
__device__ float g_v[MROWS * DIM];
__device__ float g_ctx[MROWS * DIM];

// ---------------------------------------------------------------------------
// GEMM: C[M,1024] = A[M,1024] @ W[1024,1024] + bias[1024]   (all row-major)
// 128x128 block tile, BK=8, 256 threads, 8x8 micro-tile, double-buffered SMEM.
// ---------------------------------------------------------------------------
__global__ __launch_bounds__(256)
void gemm_bias_kernel(const float* __restrict__ A,
                      const float* __restrict__ W,
                      const float* __restrict__ bias,
                      float* __restrict__ C) {
    const int N = DIM, K = DIM;
    __shared__ float As[2][8][128];   // transposed A tile: As[buf][k][row]
    __shared__ float Bs[2][8][128];   // Bs[buf][k][col]

    const int tid = threadIdx.x;
    const int rm = blockIdx.y * 128;
    const int cn = blockIdx.x * 128;
    const int ty = tid >> 4;        // 0..15
    const int tx = tid & 15;        // 0..15

    const int a_row = tid >> 1;           // 0..127
    const int a_col = (tid & 1) << 2;     // 0 or 4
    const int b_row = tid >> 5;           // 0..7
    const int b_col = (tid & 31) << 2;    // 0..124

    const float* Ap = A + (size_t)(rm + a_row) * K + a_col;
    const float* Wp = W + (size_t)b_row * N + cn + b_col;

    float acc[8][8];
#pragma unroll
    for (int i = 0; i < 8; i++)
#pragma unroll
        for (int j = 0; j < 8; j++) acc[i][j] = 0.f;

    // prologue: tile 0 -> buffer 0
    {
        float4 av = *(const float4*)(Ap);
        float4 bv = *(const float4*)(Wp);
        As[0][a_col + 0][a_row] = av.x;
        As[0][a_col + 1][a_row] = av.y;
        As[0][a_col + 2][a_row] = av.z;
        As[0][a_col + 3][a_row] = av.w;
        *(float4*)&Bs[0][b_row][b_col] = bv;
    }
    __syncthreads();

    const int NT = K / 8;   // 128 tiles
    for (int it = 0; it < NT; it++) {
        const int buf = it & 1;
        float4 av2, bv2;
        const bool more = (it + 1 < NT);
        if (more) {
            av2 = *(const float4*)(Ap + (it + 1) * 8);
            bv2 = *(const float4*)(Wp + (size_t)(it + 1) * 8 * N);
        }

#pragma unroll
        for (int k = 0; k < 8; k++) {
            float4 a0 = *(const float4*)&As[buf][k][ty * 4];
            float4 a1 = *(const float4*)&As[buf][k][ty * 4 + 64];
            float4 b0 = *(const float4*)&Bs[buf][k][tx * 4];
            float4 b1 = *(const float4*)&Bs[buf][k][tx * 4 + 64];
            float ar[8] = {a0.x, a0.y, a0.z, a0.w, a1.x, a1.y, a1.z, a1.w};
            float br[8] = {b0.x, b0.y, b0.z, b0.w, b1.x, b1.y, b1.z, b1.w};
#pragma unroll
            for (int i = 0; i < 8; i++)
#pragma unroll
                for (int j = 0; j < 8; j++)
                    acc[i][j] += ar[i] * br[j];
        }

        if (more) {
            const int nb = buf ^ 1;
            As[nb][a_col + 0][a_row] = av2.x;
            As[nb][a_col + 1][a_row] = av2.y;
            As[nb][a_col + 2][a_row] = av2.z;
            As[nb][a_col + 3][a_row] = av2.w;
            *(float4*)&Bs[nb][b_row][b_col] = bv2;
            __syncthreads();
        }
    }

    // epilogue: add bias, vectorized stores
    float4 bb0 = *(const float4*)(bias + cn + tx * 4);
    float4 bb1 = *(const float4*)(bias + cn + 64 + tx * 4);
#pragma unroll
    for (int ih = 0; ih < 2; ih++) {
#pragma unroll
        for (int ii = 0; ii < 4; ii++) {
            const int i = ih * 4 + ii;
            const int row = rm + ih * 64 + ty * 4 + ii;
            float4 o0, o1;
            o0.x = acc[i][0] + bb0.x;
            o0.y = acc[i][1] + bb0.y;
            o0.z = acc[i][2] + bb0.z;
            o0.w = acc[i][3] + bb0.w;
            o1.x = acc[i][4] + bb1.x;
            o1.y = acc[i][5] + bb1.y;
            o1.z = acc[i][6] + bb1.z;
            o1.w = acc[i][7] + bb1.w;
            *(float4*)(C + (size_t)row * N + cn + tx * 4)      = o0;
            *(float4*)(C + (size_t)row * N + cn + 64 + tx * 4) = o1;
        }
    }
}

// ---------------------------------------------------------------------------
// Flash attention, fp32, D=64, 64-query block per CTA, 64-key tiles.
// Grid: (S/64, H, B) = (32, 16, 4). 256 threads.
// All inner-loop shared traffic is LDS.128 / STS.128:
//   qst [64][68]  q TRANSPOSED:  qst[d][r]   (pre-scaled by 1/8)
//   kts [64][68]  k TRANSPOSED:  kts[d][c]
//   vs  [64][64]  v row-major:   vs[c][d]
//   ss  [64][68]  scores / probs (pad 68 = 17*16B keeps float4 alignment,
//                 and all access patterns hit the 4-wavefront minimum)
//   maskv[64]
// ---------------------------------------------------------------------------
#define QP 68
#define ATTN_SMEM_FLOATS (64*QP + 64*QP + 64*64 + 64*QP + 64)
#define ATTN_SMEM_BYTES  (ATTN_SMEM_FLOATS * 4)

__global__ __launch_bounds__(256)
void flash_attn_kernel(const float* __restrict__ maskg,
                       const float* __restrict__ qg_,
                       const float* __restrict__ kg_,
                       const float* __restrict__ vg_,
                       float* __restrict__ ctxg) {
    extern __shared__ float sm[];
    float* qst   = sm;                    // 64*68
    float* kts   = qst + 64 * QP;         // 64*68
    float* vs    = kts + 64 * QP;         // 64*64
    float* ss    = vs + 64 * 64;          // 64*68
    float* maskv = ss + 64 * QP;          // 64

    const int tid = threadIdx.x;
    const int qt = blockIdx.x, h = blockIdx.y, b = blockIdx.z;
    const int q0 = qt * 64;
    const int ty = tid >> 4, tx = tid & 15;   // S-compute mapping (4x4 tile)
    const int r_ = tid >> 2, q4 = tid & 3;    // softmax / o-update mapping
    const int cb = (tid & 15) * 4;            // 4x4-block transpose mapping
    const int db = (tid >> 4) * 4;

    // load q tile, transpose via 4x4 register blocks, pre-scale by 1/sqrt(64)
    {
        const float* qg = qg_ + ((size_t)(b * SS + q0)) * DIM + h * HD;
        float4 t0 = *(const float4*)(qg + (size_t)(cb + 0) * DIM + db);
        float4 t1 = *(const float4*)(qg + (size_t)(cb + 1) * DIM + db);
        float4 t2 = *(const float4*)(qg + (size_t)(cb + 2) * DIM + db);
        float4 t3 = *(const float4*)(qg + (size_t)(cb + 3) * DIM + db);
        const float s = 0.125f;
        float4 w;
        w.x = t0.x * s; w.y = t1.x * s; w.z = t2.x * s; w.w = t3.x * s;
        *(float4*)&qst[(db + 0) * QP + cb] = w;
        w.x = t0.y * s; w.y = t1.y * s; w.z = t2.y * s; w.w = t3.y * s;
        *(float4*)&qst[(db + 1) * QP + cb] = w;
        w.x = t0.z * s; w.y = t1.z * s; w.z = t2.z * s; w.w = t3.z * s;
        *(float4*)&qst[(db + 2) * QP + cb] = w;
        w.x = t0.w * s; w.y = t1.w * s; w.z = t2.w * s; w.w = t3.w * s;
        *(float4*)&qst[(db + 3) * QP + cb] = w;
    }

    float m = -1e30f, l = 0.f;
    float o[16];
#pragma unroll
    for (int j = 0; j < 16; j++) o[j] = 0.f;

    for (int kt = 0; kt < 32; kt++) {
        __syncthreads();   // prior iteration fully consumed kts/vs/ss

        const float* kg = kg_ + ((size_t)(b * SS + kt * 64)) * DIM + h * HD;
        const float* vg = vg_ + ((size_t)(b * SS + kt * 64)) * DIM + h * HD;

        // K: 4x4 register-block transpose -> kts[d][c]  (STS.128, conflict-free)
        {
            float4 t0 = *(const float4*)(kg + (size_t)(cb + 0) * DIM + db);
            float4 t1 = *(const float4*)(kg + (size_t)(cb + 1) * DIM + db);
            float4 t2 = *(const float4*)(kg + (size_t)(cb + 2) * DIM + db);
            float4 t3 = *(const float4*)(kg + (size_t)(cb + 3) * DIM + db);
            float4 w;
            w.x = t0.x; w.y = t1.x; w.z = t2.x; w.w = t3.x;
            *(float4*)&kts[(db + 0) * QP + cb] = w;
            w.x = t0.y; w.y = t1.y; w.z = t2.y; w.w = t3.y;
            *(float4*)&kts[(db + 1) * QP + cb] = w;
            w.x = t0.z; w.y = t1.z; w.z = t2.z; w.w = t3.z;
            *(float4*)&kts[(db + 2) * QP + cb] = w;
            w.x = t0.w; w.y = t1.w; w.z = t2.w; w.w = t3.w;
            *(float4*)&kts[(db + 3) * QP + cb] = w;
        }
        // V: straight row-major copy
#pragma unroll
        for (int u = 0; u < 4; u++) {
            int idx = tid + u * 256;
            int c   = idx >> 4;
            int d4  = (idx & 15) << 2;
            *(float4*)&vs[c * 64 + d4] = *(const float4*)(vg + (size_t)c * DIM + d4);
        }
        if (tid < 64)
            maskv[tid] = maskg[(size_t)b * SS + kt * 64 + tid] * -1e9f;
        __syncthreads();

        // S = q @ k^T  (each thread: 4x4 tile); 2x LDS.128 per d-step
        float sacc[4][4];
#pragma unroll
        for (int i = 0; i < 4; i++)
#pragma unroll
            for (int j = 0; j < 4; j++) sacc[i][j] = 0.f;

#pragma unroll 8
        for (int d = 0; d < 64; d++) {
            float4 a = *(const float4*)&qst[d * QP + ty * 4];
            float4 bq = *(const float4*)&kts[d * QP + tx * 4];
            sacc[0][0] += a.x * bq.x; sacc[0][1] += a.x * bq.y; sacc[0][2] += a.x * bq.z; sacc[0][3] += a.x * bq.w;
            sacc[1][0] += a.y * bq.x; sacc[1][1] += a.y * bq.y; sacc[1][2] += a.y * bq.z; sacc[1][3] += a.y * bq.w;
            sacc[2][0] += a.z * bq.x; sacc[2][1] += a.z * bq.y; sacc[2][2] += a.z * bq.z; sacc[2][3] += a.z * bq.w;
            sacc[3][0] += a.w * bq.x; sacc[3][1] += a.w * bq.y; sacc[3][2] += a.w * bq.z; sacc[3][3] += a.w * bq.w;
        }
        {
            float4 mv = *(const float4*)&maskv[tx * 4];
#pragma unroll
            for (int i = 0; i < 4; i++) {
                float4 w;
                w.x = sacc[i][0] + mv.x;
                w.y = sacc[i][1] + mv.y;
                w.z = sacc[i][2] + mv.z;
                w.w = sacc[i][3] + mv.w;
                *(float4*)&ss[(ty * 4 + i) * QP + tx * 4] = w;
            }
        }
        __syncthreads();

        // online softmax: row r_ handled by its 4 consecutive lanes (float4 I/O)
        float4 pv[4];
#pragma unroll
        for (int j4 = 0; j4 < 4; j4++)
            pv[j4] = *(const float4*)&ss[r_ * QP + q4 * 16 + j4 * 4];

        float lmax = -1e30f;
#pragma unroll
        for (int j4 = 0; j4 < 4; j4++) {
            lmax = fmaxf(lmax, fmaxf(fmaxf(pv[j4].x, pv[j4].y), fmaxf(pv[j4].z, pv[j4].w)));
        }
        lmax = fmaxf(lmax, __shfl_xor_sync(0xffffffffu, lmax, 1));
        lmax = fmaxf(lmax, __shfl_xor_sync(0xffffffffu, lmax, 2));
        float mnew = fmaxf(m, lmax);

        float lsum = 0.f;
#pragma unroll
        for (int j4 = 0; j4 < 4; j4++) {
            pv[j4].x = __expf(pv[j4].x - mnew);
            pv[j4].y = __expf(pv[j4].y - mnew);
            pv[j4].z = __expf(pv[j4].z - mnew);
            pv[j4].w = __expf(pv[j4].w - mnew);
            lsum += pv[j4].x + pv[j4].y + pv[j4].z + pv[j4].w;
            *(float4*)&ss[r_ * QP + q4 * 16 + j4 * 4] = pv[j4];
        }
        lsum += __shfl_xor_sync(0xffffffffu, lsum, 1);
        lsum += __shfl_xor_sync(0xffffffffu, lsum, 2);

        float alpha = __expf(m - mnew);
        l = l * alpha + lsum;
        m = mnew;
#pragma unroll
        for (int j = 0; j < 16; j++) o[j] *= alpha;

        __syncwarp();   // quad-mates' probability writes visible

        // o += P @ V  (thread owns row r_, dim slice q4*16..+15); p loaded float4
#pragma unroll 4
        for (int c4 = 0; c4 < 64; c4 += 4) {
            float4 pq = *(const float4*)&ss[r_ * QP + c4];
            float pr[4] = {pq.x, pq.y, pq.z, pq.w};
#pragma unroll
            for (int jc = 0; jc < 4; jc++) {
                const float p = pr[jc];
                const float* vrow = &vs[(c4 + jc) * 64 + q4 * 16];
                float4 v0 = *(const float4*)(vrow + 0);
                float4 v1 = *(const float4*)(vrow + 4);
                float4 v2 = *(const float4*)(vrow + 8);
                float4 v3 = *(const float4*)(vrow + 12);
                o[0]  += p * v0.x; o[1]  += p * v0.y; o[2]  += p * v0.z; o[3]  += p * v0.w;
                o[4]  += p * v1.x; o[5]  += p * v1.y; o[6]  += p * v1.z; o[7]  += p * v1.w;
                o[8]  += p * v2.x; o[9]  += p * v2.y; o[10] += p * v2.z; o[11] += p * v2.w;
                o[12] += p * v3.x; o[13] += p * v3.y; o[14] += p * v3.z; o[15] += p * v3.w;
            }
        }
    }

    // epilogue: normalize and write back in [B,S,DIM] layout (heads re-merged)
    float inv = 1.f / l;
    float* og = ctxg + ((size_t)(b * SS + q0 + r_)) * DIM + h * HD + q4 * 16;
#pragma unroll
    for (int j4 = 0; j4 < 4; j4++) {
        float4 w;
        w.x = o[j4 * 4 + 0] * inv;
        w.y = o[j4 * 4 + 1] * inv;
        w.z = o[j4 * 4 + 2] * inv;
        w.w = o[j4 * 4 + 3] * inv;
        *(float4*)(og + j4 * 4) = w;
    }
}

// ---------------------------------------------------------------------------
extern "C" void kernel_launch(void* const* d_in, const int* in_sizes, int n_in,
                              void* d_out, int out_size) {
    const float* Q    = (const float*)d_in[0];
    const float* K    = (const float*)d_in[1];
    const float* V    = (const float*)d_in[2];
    const float* mask = (const float*)d_in[3];
    const float* Wq   = (const float*)d_in[4];
    const float* bq   = (const float*)d_in[5];
    const float* Wk   = (const float*)d_in[6];
    const float* bk   = (const float*)d_in[7];
    const float* Wv   = (const float*)d_in[8];
    const float* bv   = (const float*)d_in[9];
    const float* Wo   = (const float*)d_in[10];
    const float* bo   = (const float*)d_in[11];
    float* out = (float*)d_out;

    float *gq, *gk, *gv, *gctx;
    cudaGetSymbolAddress((void**)&gq,   g_q);
    cudaGetSymbolAddress((void**)&gk,   g_k);
    cudaGetSymbolAddress((void**)&gv,   g_v);
    cudaGetSymbolAddress((void**)&gctx, g_ctx);

    cudaFuncSetAttribute(flash_attn_kernel,
                         cudaFuncAttributeMaxDynamicSharedMemorySize,
                         ATTN_SMEM_BYTES);

    dim3 gemm_grid(DIM / 128, MROWS / 128);   // (8, 64)

    gemm_bias_kernel<<<gemm_grid, 256>>>(Q, Wq, bq, gq);
    gemm_bias_kernel<<<gemm_grid, 256>>>(K, Wk, bk, gk);
    gemm_bias_kernel<<<gemm_grid, 256>>>(V, Wv, bv, gv);

    flash_attn_kernel<<<dim3(SS / 64, NH, BB), 256, ATTN_SMEM_BYTES>>>(
        mask, gq, gk, gv, gctx);

    gemm_bias_kernel<<<gemm_grid, 256>>>(gctx, Wo, bo, out);
}

// round 17
// speedup vs baseline: 2.0693x; 1.9287x over previous
#include <cuda_runtime.h>
#include <math.h>

// Problem constants
#define BB   4
#define SS   2048
#define DIM  1024
#define NH   16
#define HD   64
#define MROWS (BB * SS)   // 8192

// Scratch for projected q/k/v and attention context ([B,S,DIM] layout each).
__device__ float g_q[MROWS * DIM];
__device__ float g_k[MROWS * DIM];
__device__ float g_v[MROWS * DIM];
__device__ float g_ctx[MROWS * DIM];

// ---------------------------------------------------------------------------
// GEMM: C[M,1024] = A[M,1024] @ W[1024,1024] + bias[1024]   (all row-major)
// 128x128 block tile, BK=8, 256 threads, 8x8 micro-tile, double-buffered SMEM.
// ---------------------------------------------------------------------------
__global__ __launch_bounds__(256)
void gemm_bias_kernel(const float* __restrict__ A,
                      const float* __restrict__ W,
                      const float* __restrict__ bias,
                      float* __restrict__ C) {
    const int N = DIM, K = DIM;
    __shared__ float As[2][8][128];   // transposed A tile: As[buf][k][row]
    __shared__ float Bs[2][8][128];   // Bs[buf][k][col]

    const int tid = threadIdx.x;
    const int rm = blockIdx.y * 128;
    const int cn = blockIdx.x * 128;
    const int ty = tid >> 4;        // 0..15
    const int tx = tid & 15;        // 0..15

    const int a_row = tid >> 1;           // 0..127
    const int a_col = (tid & 1) << 2;     // 0 or 4
    const int b_row = tid >> 5;           // 0..7
    const int b_col = (tid & 31) << 2;    // 0..124

    const float* Ap = A + (size_t)(rm + a_row) * K + a_col;
    const float* Wp = W + (size_t)b_row * N + cn + b_col;

    float acc[8][8];
#pragma unroll
    for (int i = 0; i < 8; i++)
#pragma unroll
        for (int j = 0; j < 8; j++) acc[i][j] = 0.f;

    // prologue: tile 0 -> buffer 0
    {
        float4 av = *(const float4*)(Ap);
        float4 bv = *(const float4*)(Wp);
        As[0][a_col + 0][a_row] = av.x;
        As[0][a_col + 1][a_row] = av.y;
        As[0][a_col + 2][a_row] = av.z;
        As[0][a_col + 3][a_row] = av.w;
        *(float4*)&Bs[0][b_row][b_col] = bv;
    }
    __syncthreads();

    const int NT = K / 8;   // 128 tiles
    for (int it = 0; it < NT; it++) {
        const int buf = it & 1;
        float4 av2, bv2;
        const bool more = (it + 1 < NT);
        if (more) {
            av2 = *(const float4*)(Ap + (it + 1) * 8);
            bv2 = *(const float4*)(Wp + (size_t)(it + 1) * 8 * N);
        }

#pragma unroll
        for (int k = 0; k < 8; k++) {
            float4 a0 = *(const float4*)&As[buf][k][ty * 4];
            float4 a1 = *(const float4*)&As[buf][k][ty * 4 + 64];
            float4 b0 = *(const float4*)&Bs[buf][k][tx * 4];
            float4 b1 = *(const float4*)&Bs[buf][k][tx * 4 + 64];
            float ar[8] = {a0.x, a0.y, a0.z, a0.w, a1.x, a1.y, a1.z, a1.w};
            float br[8] = {b0.x, b0.y, b0.z, b0.w, b1.x, b1.y, b1.z, b1.w};
#pragma unroll
            for (int i = 0; i < 8; i++)
#pragma unroll
                for (int j = 0; j < 8; j++)
                    acc[i][j] += ar[i] * br[j];
        }

        if (more) {
            const int nb = buf ^ 1;
            As[nb][a_col + 0][a_row] = av2.x;
            As[nb][a_col + 1][a_row] = av2.y;
            As[nb][a_col + 2][a_row] = av2.z;
            As[nb][a_col + 3][a_row] = av2.w;
            *(float4*)&Bs[nb][b_row][b_col] = bv2;
            __syncthreads();
        }
    }

    // epilogue: add bias, vectorized stores
    float4 bb0 = *(const float4*)(bias + cn + tx * 4);
    float4 bb1 = *(const float4*)(bias + cn + 64 + tx * 4);
#pragma unroll
    for (int ih = 0; ih < 2; ih++) {
#pragma unroll
        for (int ii = 0; ii < 4; ii++) {
            const int i = ih * 4 + ii;
            const int row = rm + ih * 64 + ty * 4 + ii;
            float4 o0, o1;
            o0.x = acc[i][0] + bb0.x;
            o0.y = acc[i][1] + bb0.y;
            o0.z = acc[i][2] + bb0.z;
            o0.w = acc[i][3] + bb0.w;
            o1.x = acc[i][4] + bb1.x;
            o1.y = acc[i][5] + bb1.y;
            o1.z = acc[i][6] + bb1.z;
            o1.w = acc[i][7] + bb1.w;
            *(float4*)(C + (size_t)row * N + cn + tx * 4)      = o0;
            *(float4*)(C + (size_t)row * N + cn + 64 + tx * 4) = o1;
        }
    }
}

// ---------------------------------------------------------------------------
// Flash attention v2: 128-query block x 128-key tiles, 256 threads, 1 CTA/SM.
// S-compute: 8x8 register tile (1.0 B/FMA). P@V: 8x4 register tile with
// broadcast scalar p-loads (1.5 B/FMA). Softmax: 2 threads per row.
// SMEM (floats):
//   qst [64][132]   q transposed [d][r], pre-scaled 1/8
//   kts [64][132]   k transposed [d][c]
//   vs  [128][64]   v row-major
//   ss  [128][132]  scores / probs
//   maskv[128], alpha_s[128], linv_s[128]
// ---------------------------------------------------------------------------
#define TP 132
#define SP 132
#define ATTN_SMEM_FLOATS (64*TP + 64*TP + 128*64 + 128*SP + 128*3)
#define ATTN_SMEM_BYTES  (ATTN_SMEM_FLOATS * 4)

__global__ __launch_bounds__(256, 1)
void flash_attn_kernel(const float* __restrict__ maskg,
                       const float* __restrict__ qg_,
                       const float* __restrict__ kg_,
                       const float* __restrict__ vg_,
                       float* __restrict__ ctxg) {
    extern __shared__ float sm[];
    float* qst     = sm;                    // 64*132
    float* kts     = qst + 64 * TP;         // 64*132
    float* vs      = kts + 64 * TP;         // 128*64
    float* ss      = vs + 128 * 64;         // 128*132
    float* maskv   = ss + 128 * SP;         // 128
    float* alpha_s = maskv + 128;           // 128
    float* linv_s  = alpha_s + 128;         // 128

    const int tid = threadIdx.x;
    const int qt = blockIdx.x, h = blockIdx.y, b = blockIdx.z;
    const int q0 = qt * 128;
    const int ty = tid >> 4, tx = tid & 15;   // micro-tile mapping
    const int cb = (tid & 31) * 4;            // transpose: row/col block 0..124
    const int db = (tid >> 5) * 8;            // transpose: dim block 0..56
    const int r_ = tid >> 1, half = tid & 1;  // softmax mapping (2 thr/row)

    // ---- Q load + transpose (128 rows x 64 dims), pre-scale 1/sqrt(64) ----
    {
        const float* qg = qg_ + ((size_t)(b * SS + q0)) * DIM + h * HD;
        const float s = 0.125f;
        float4 r0a = *(const float4*)(qg + (size_t)(cb + 0) * DIM + db);
        float4 r0b = *(const float4*)(qg + (size_t)(cb + 0) * DIM + db + 4);
        float4 r1a = *(const float4*)(qg + (size_t)(cb + 1) * DIM + db);
        float4 r1b = *(const float4*)(qg + (size_t)(cb + 1) * DIM + db + 4);
        float4 r2a = *(const float4*)(qg + (size_t)(cb + 2) * DIM + db);
        float4 r2b = *(const float4*)(qg + (size_t)(cb + 2) * DIM + db + 4);
        float4 r3a = *(const float4*)(qg + (size_t)(cb + 3) * DIM + db);
        float4 r3b = *(const float4*)(qg + (size_t)(cb + 3) * DIM + db + 4);
        *(float4*)&qst[(db + 0) * TP + cb] = make_float4(r0a.x*s, r1a.x*s, r2a.x*s, r3a.x*s);
        *(float4*)&qst[(db + 1) * TP + cb] = make_float4(r0a.y*s, r1a.y*s, r2a.y*s, r3a.y*s);
        *(float4*)&qst[(db + 2) * TP + cb] = make_float4(r0a.z*s, r1a.z*s, r2a.z*s, r3a.z*s);
        *(float4*)&qst[(db + 3) * TP + cb] = make_float4(r0a.w*s, r1a.w*s, r2a.w*s, r3a.w*s);
        *(float4*)&qst[(db + 4) * TP + cb] = make_float4(r0b.x*s, r1b.x*s, r2b.x*s, r3b.x*s);
        *(float4*)&qst[(db + 5) * TP + cb] = make_float4(r0b.y*s, r1b.y*s, r2b.y*s, r3b.y*s);
        *(float4*)&qst[(db + 6) * TP + cb] = make_float4(r0b.z*s, r1b.z*s, r2b.z*s, r3b.z*s);
        *(float4*)&qst[(db + 7) * TP + cb] = make_float4(r0b.w*s, r1b.w*s, r2b.w*s, r3b.w*s);
    }

    float m = -1e30f, l = 0.f;
    float o[8][4];
#pragma unroll
    for (int i = 0; i < 8; i++)
#pragma unroll
        for (int j = 0; j < 4; j++) o[i][j] = 0.f;

    for (int kt = 0; kt < SS / 128; kt++) {
        __syncthreads();   // prior iteration fully consumed kts/vs/ss

        const float* kg = kg_ + ((size_t)(b * SS + kt * 128)) * DIM + h * HD;
        const float* vg = vg_ + ((size_t)(b * SS + kt * 128)) * DIM + h * HD;

        // K transpose -> kts[d][c]
        {
            float4 r0a = *(const float4*)(kg + (size_t)(cb + 0) * DIM + db);
            float4 r0b = *(const float4*)(kg + (size_t)(cb + 0) * DIM + db + 4);
            float4 r1a = *(const float4*)(kg + (size_t)(cb + 1) * DIM + db);
            float4 r1b = *(const float4*)(kg + (size_t)(cb + 1) * DIM + db + 4);
            float4 r2a = *(const float4*)(kg + (size_t)(cb + 2) * DIM + db);
            float4 r2b = *(const float4*)(kg + (size_t)(cb + 2) * DIM + db + 4);
            float4 r3a = *(const float4*)(kg + (size_t)(cb + 3) * DIM + db);
            float4 r3b = *(const float4*)(kg + (size_t)(cb + 3) * DIM + db + 4);
            *(float4*)&kts[(db + 0) * TP + cb] = make_float4(r0a.x, r1a.x, r2a.x, r3a.x);
            *(float4*)&kts[(db + 1) * TP + cb] = make_float4(r0a.y, r1a.y, r2a.y, r3a.y);
            *(float4*)&kts[(db + 2) * TP + cb] = make_float4(r0a.z, r1a.z, r2a.z, r3a.z);
            *(float4*)&kts[(db + 3) * TP + cb] = make_float4(r0a.w, r1a.w, r2a.w, r3a.w);
            *(float4*)&kts[(db + 4) * TP + cb] = make_float4(r0b.x, r1b.x, r2b.x, r3b.x);
            *(float4*)&kts[(db + 5) * TP + cb] = make_float4(r0b.y, r1b.y, r2b.y, r3b.y);
            *(float4*)&kts[(db + 6) * TP + cb] = make_float4(r0b.z, r1b.z, r2b.z, r3b.z);
            *(float4*)&kts[(db + 7) * TP + cb] = make_float4(r0b.w, r1b.w, r2b.w, r3b.w);
        }
        // V: straight row-major copy (128 x 64)
#pragma unroll
        for (int u = 0; u < 8; u++) {
            int idx = tid + u * 256;         // 0..2047
            int c   = idx >> 4;
            int d4  = (idx & 15) << 2;
            *(float4*)&vs[c * 64 + d4] = *(const float4*)(vg + (size_t)c * DIM + d4);
        }
        if (tid < 128)
            maskv[tid] = maskg[(size_t)b * SS + kt * 128 + tid] * -1e9f;
        __syncthreads();

        // ---- S = q @ k^T  (8x8 register tile per thread) ----
        {
            float acc[8][8];
#pragma unroll
            for (int i = 0; i < 8; i++)
#pragma unroll
                for (int j = 0; j < 8; j++) acc[i][j] = 0.f;

#pragma unroll 4
            for (int d = 0; d < 64; d++) {
                float4 a0 = *(const float4*)&qst[d * TP + ty * 8];
                float4 a1 = *(const float4*)&qst[d * TP + ty * 8 + 4];
                float4 b0 = *(const float4*)&kts[d * TP + tx * 8];
                float4 b1 = *(const float4*)&kts[d * TP + tx * 8 + 4];
                float ar[8] = {a0.x, a0.y, a0.z, a0.w, a1.x, a1.y, a1.z, a1.w};
                float br[8] = {b0.x, b0.y, b0.z, b0.w, b1.x, b1.y, b1.z, b1.w};
#pragma unroll
                for (int i = 0; i < 8; i++)
#pragma unroll
                    for (int j = 0; j < 8; j++)
                        acc[i][j] += ar[i] * br[j];
            }

            float4 mv0 = *(const float4*)&maskv[tx * 8];
            float4 mv1 = *(const float4*)&maskv[tx * 8 + 4];
#pragma unroll
            for (int i = 0; i < 8; i++) {
                *(float4*)&ss[(ty * 8 + i) * SP + tx * 8] =
                    make_float4(acc[i][0] + mv0.x, acc[i][1] + mv0.y,
                                acc[i][2] + mv0.z, acc[i][3] + mv0.w);
                *(float4*)&ss[(ty * 8 + i) * SP + tx * 8 + 4] =
                    make_float4(acc[i][4] + mv1.x, acc[i][5] + mv1.y,
                                acc[i][6] + mv1.z, acc[i][7] + mv1.w);
            }
        }
        __syncthreads();

        // ---- online softmax: 2 threads per row, 64 cols each ----
        {
            float* rowp = ss + r_ * SP + half * 64;
            float lmax = -1e30f;
#pragma unroll
            for (int j4 = 0; j4 < 16; j4++) {
                float4 x = *(const float4*)(rowp + j4 * 4);
                lmax = fmaxf(lmax, fmaxf(fmaxf(x.x, x.y), fmaxf(x.z, x.w)));
            }
            lmax = fmaxf(lmax, __shfl_xor_sync(0xffffffffu, lmax, 1));
            float mnew = fmaxf(m, lmax);

            float lsum = 0.f;
#pragma unroll
            for (int j4 = 0; j4 < 16; j4++) {
                float4 x = *(const float4*)(rowp + j4 * 4);
                x.x = __expf(x.x - mnew);
                x.y = __expf(x.y - mnew);
                x.z = __expf(x.z - mnew);
                x.w = __expf(x.w - mnew);
                *(float4*)(rowp + j4 * 4) = x;
                lsum += x.x + x.y + x.z + x.w;
            }
            lsum += __shfl_xor_sync(0xffffffffu, lsum, 1);

            float alpha = __expf(m - mnew);
            l = l * alpha + lsum;
            m = mnew;
            if (half == 0) alpha_s[r_] = alpha;
        }
        __syncthreads();

        // ---- o = o*alpha + P @ V  (8 rows x 4 dims per thread) ----
        {
            float as_[8];
#pragma unroll
            for (int i = 0; i < 8; i++) as_[i] = alpha_s[ty * 8 + i];
#pragma unroll
            for (int i = 0; i < 8; i++) {
                o[i][0] *= as_[i]; o[i][1] *= as_[i];
                o[i][2] *= as_[i]; o[i][3] *= as_[i];
            }
#pragma unroll 2
            for (int c = 0; c < 128; c++) {
                float4 v = *(const float4*)&vs[c * 64 + tx * 4];
#pragma unroll
                for (int i = 0; i < 8; i++) {
                    float p = ss[(ty * 8 + i) * SP + c];
                    o[i][0] += p * v.x;
                    o[i][1] += p * v.y;
                    o[i][2] += p * v.z;
                    o[i][3] += p * v.w;
                }
            }
        }
    }

    // ---- epilogue: normalize and write back ----
    if (half == 0) linv_s[r_] = 1.f / l;
    __syncthreads();
#pragma unroll
    for (int i = 0; i < 8; i++) {
        float li = linv_s[ty * 8 + i];
        float4 w = make_float4(o[i][0] * li, o[i][1] * li,
                               o[i][2] * li, o[i][3] * li);
        *(float4*)(ctxg + ((size_t)(b * SS + q0 + ty * 8 + i)) * DIM
                   + h * HD + tx * 4) = w;
    }
}

// ---------------------------------------------------------------------------
extern "C" void kernel_launch(void* const* d_in, const int* in_sizes, int n_in,
                              void* d_out, int out_size) {
    const float* Q    = (const float*)d_in[0];
    const float* K    = (const float*)d_in[1];
    const float* V    = (const float*)d_in[2];
    const float* mask = (const float*)d_in[3];
    const float* Wq   = (const float*)d_in[4];
    const float* bq   = (const float*)d_in[5];
    const float* Wk   = (const float*)d_in[6];
    const float* bk   = (const float*)d_in[7];
    const float* Wv   = (const float*)d_in[8];
    const float* bv   = (const float*)d_in[9];
    const float* Wo   = (const float*)d_in[10];
    const float* bo   = (const float*)d_in[11];
    float* out = (float*)d_out;

    float *gq, *gk, *gv, *gctx;
    cudaGetSymbolAddress((void**)&gq,   g_q);
    cudaGetSymbolAddress((void**)&gk,   g_k);
    cudaGetSymbolAddress((void**)&gv,   g_v);
    cudaGetSymbolAddress((void**)&gctx, g_ctx);

    cudaFuncSetAttribute(flash_attn_kernel,
                         cudaFuncAttributeMaxDynamicSharedMemorySize,
                         ATTN_SMEM_BYTES);

    dim3 gemm_grid(DIM / 128, MROWS / 128);   // (8, 64)

    gemm_bias_kernel<<<gemm_grid, 256>>>(Q, Wq, bq, gq);
    gemm_bias_kernel<<<gemm_grid, 256>>>(K, Wk, bk, gk);
    gemm_bias_kernel<<<gemm_grid, 256>>>(V, Wv, bv, gv);

    flash_attn_kernel<<<dim3(SS / 128, NH, BB), 256, ATTN_SMEM_BYTES>>>(
        mask, gq, gk, gv, gctx);

    gemm_bias_kernel<<<gemm_grid, 256>>>(gctx, Wo, bo, out);
}